// round 1
// baseline (speedup 1.0000x reference)
#include <cuda_runtime.h>
#include <math.h>

#define Bc 4
#define Sq 2048
#define Dm 1024
#define Hh 16
#define HDIM 64
#define Ff 4096
#define Ee 8
#define Kk 2
#define Tt (Bc*Sq)   /* 8192 tokens */

// ------------------------- scratch (device globals; no allocs allowed) ----
__device__ float g_q  [(size_t)Tt*Dm];
__device__ float g_k  [(size_t)Tt*Dm];
__device__ float g_v  [(size_t)Tt*Dm];
__device__ float g_att[(size_t)Tt*Dm];
__device__ float g_prj[(size_t)Tt*Dm];
__device__ float g_x1 [(size_t)Tt*Dm];
__device__ float g_moe[(size_t)Tt*Dm];
__device__ float g_h  [(size_t)Tt*Kk*Ff];     // packed expert hidden (16384 x 4096)
__device__ int   g_tok[Ee*Tt];
__device__ float g_wt [Ee*Tt];
__device__ int   g_cnt[Ee];
__device__ int   g_off[Ee];
__device__ float g_gsum[Ee];

// ------------------------- generic 128x128x8 fp32 GEMM ---------------------
// MODE 0: C = A @ B + bias                     (A [M,Kd] row-major)
// MODE 1: expert FFN1: A rows gathered via token list, GELU epilogue,
//         per-expert weight/bias slice, C packed at off[e]
// MODE 2: expert FFN2: A = packed h, epilogue scatter-add w * (acc+bias)
//         into moe[token]
template<int MODE>
__global__ __launch_bounds__(256, 2)
void gemm_kernel(const float* __restrict__ A,
                 const float* __restrict__ Bm,
                 const float* __restrict__ bias,
                 float* __restrict__ C,
                 int M, int N, int Kd,
                 const int* __restrict__ cnt,
                 const int* __restrict__ off,
                 const int* __restrict__ tokl,
                 const float* __restrict__ wtl)
{
    const int e  = blockIdx.z;
    const int m0 = blockIdx.y * 128;
    const int n0 = blockIdx.x * 128;

    int Me = M;
    int hbase = 0;
    const float* Bp = Bm;
    const float* bp = bias;
    if (MODE == 1 || MODE == 2) {
        Me = cnt[e];
        if (m0 >= Me) return;
        Bp = Bm + (size_t)e * Kd * N;
        bp = bias + (size_t)e * N;
        hbase = off[e];
    }

    __shared__ float As[8][128];
    __shared__ float Bs[8][128];

    const int tid = threadIdx.x;
    const int tx = tid & 15;
    const int ty = tid >> 4;

    const int la_row = tid >> 1;        // 0..127
    const int la_k   = (tid & 1) * 4;   // 0 or 4
    const int lb_k   = tid >> 5;        // 0..7
    const int lb_c   = (tid & 31) * 4;  // 0..124

    const float* Arow = A;  // dummy init
    bool a_ok;
    {
        int ar = m0 + la_row;
        if (MODE == 0) {
            a_ok = (ar < M);
            if (a_ok) Arow = A + (size_t)ar * Kd;
        } else if (MODE == 1) {
            a_ok = (ar < Me);
            if (a_ok) Arow = A + (size_t)tokl[e*Tt + ar] * Kd;
        } else {
            a_ok = (ar < Me);
            if (a_ok) Arow = A + (size_t)(hbase + ar) * Kd;
        }
    }

    float acc[8][8];
    #pragma unroll
    for (int i = 0; i < 8; i++)
        #pragma unroll
        for (int j = 0; j < 8; j++) acc[i][j] = 0.f;

    for (int k0 = 0; k0 < Kd; k0 += 8) {
        float4 av = a_ok ? *(const float4*)(Arow + k0 + la_k)
                         : make_float4(0.f, 0.f, 0.f, 0.f);
        float4 bv = *(const float4*)(Bp + (size_t)(k0 + lb_k) * N + n0 + lb_c);

        __syncthreads();
        As[la_k + 0][la_row] = av.x;
        As[la_k + 1][la_row] = av.y;
        As[la_k + 2][la_row] = av.z;
        As[la_k + 3][la_row] = av.w;
        *(float4*)&Bs[lb_k][lb_c] = bv;
        __syncthreads();

        #pragma unroll
        for (int kk = 0; kk < 8; kk++) {
            float4 a0 = *(const float4*)&As[kk][ty * 8];
            float4 a1 = *(const float4*)&As[kk][ty * 8 + 4];
            float4 b0 = *(const float4*)&Bs[kk][tx * 8];
            float4 b1 = *(const float4*)&Bs[kk][tx * 8 + 4];
            float a[8] = {a0.x, a0.y, a0.z, a0.w, a1.x, a1.y, a1.z, a1.w};
            float b[8] = {b0.x, b0.y, b0.z, b0.w, b1.x, b1.y, b1.z, b1.w};
            #pragma unroll
            for (int i = 0; i < 8; i++)
                #pragma unroll
                for (int j = 0; j < 8; j++)
                    acc[i][j] += a[i] * b[j];
        }
    }

    #pragma unroll
    for (int i = 0; i < 8; i++) {
        int r = m0 + ty * 8 + i;
        if (MODE == 0) {
            if (r < M) {
                float* Crow = C + (size_t)r * N + n0 + tx * 8;
                #pragma unroll
                for (int j = 0; j < 8; j++)
                    Crow[j] = acc[i][j] + bp[n0 + tx * 8 + j];
            }
        } else if (MODE == 1) {
            if (r < Me) {
                float* Crow = C + (size_t)(hbase + r) * N + n0 + tx * 8;
                #pragma unroll
                for (int j = 0; j < 8; j++) {
                    float vv = acc[i][j] + bp[n0 + tx * 8 + j];
                    Crow[j] = 0.5f * vv * (1.0f + erff(vv * 0.7071067811865475f));
                }
            }
        } else {
            if (r < Me) {
                int   t = tokl[e*Tt + r];
                float w = wtl [e*Tt + r];
                float* Crow = C + (size_t)t * N + n0 + tx * 8;
                #pragma unroll
                for (int j = 0; j < 8; j++)
                    atomicAdd(&Crow[j], w * (acc[i][j] + bp[n0 + tx * 8 + j]));
            }
        }
    }
}

// ------------------------- flash attention ---------------------------------
// one thread per query row; K/V tiles in smem, broadcast reads.
__global__ __launch_bounds__(128, 2)
void attn_kernel(const float* __restrict__ q, const float* __restrict__ k,
                 const float* __restrict__ v, float* __restrict__ out)
{
    const int bh = blockIdx.y;
    const int b = bh >> 4, h = bh & 15;
    const int qi = blockIdx.x * 128 + threadIdx.x;

    const float* qp = q + ((size_t)(b * Sq + qi) * Dm + h * HDIM);
    float qr[HDIM];
    #pragma unroll
    for (int d = 0; d < HDIM; d += 4) {
        float4 t = *(const float4*)(qp + d);
        qr[d] = t.x * 0.125f; qr[d+1] = t.y * 0.125f;
        qr[d+2] = t.z * 0.125f; qr[d+3] = t.w * 0.125f;
    }
    float o[HDIM];
    #pragma unroll
    for (int d = 0; d < HDIM; d++) o[d] = 0.f;
    float m = -1e30f, l = 0.f;

    __shared__ float Ks[64][HDIM];
    __shared__ float Vs[64][HDIM];

    for (int t0 = 0; t0 < Sq; t0 += 64) {
        __syncthreads();
        for (int i = threadIdx.x; i < 64 * (HDIM / 4); i += 128) {
            int r = i >> 4;
            int c = (i & 15) * 4;
            size_t base = (size_t)(b * Sq + t0 + r) * Dm + h * HDIM + c;
            *(float4*)&Ks[r][c] = *(const float4*)(k + base);
            *(float4*)&Vs[r][c] = *(const float4*)(v + base);
        }
        __syncthreads();

        float s[64];   // lives in local mem (L1-cached) to save registers
        #pragma unroll 4
        for (int j = 0; j < 64; j++) {
            float a0 = 0.f, a1 = 0.f, a2 = 0.f, a3 = 0.f;
            #pragma unroll
            for (int d = 0; d < HDIM; d += 4) {
                float4 kv = *(const float4*)&Ks[j][d];
                a0 += qr[d]   * kv.x;  a1 += qr[d+1] * kv.y;
                a2 += qr[d+2] * kv.z;  a3 += qr[d+3] * kv.w;
            }
            s[j] = (a0 + a1) + (a2 + a3);
        }
        float mt = s[0];
        #pragma unroll 8
        for (int j = 1; j < 64; j++) mt = fmaxf(mt, s[j]);
        float mnew = fmaxf(m, mt);
        float alpha = __expf(m - mnew);
        l *= alpha;
        #pragma unroll
        for (int d = 0; d < HDIM; d++) o[d] *= alpha;

        #pragma unroll 2
        for (int j = 0; j < 64; j++) {
            float p = __expf(s[j] - mnew);
            l += p;
            #pragma unroll
            for (int d = 0; d < HDIM; d += 4) {
                float4 vv = *(const float4*)&Vs[j][d];
                o[d]   += p * vv.x;  o[d+1] += p * vv.y;
                o[d+2] += p * vv.z;  o[d+3] += p * vv.w;
            }
        }
        m = mnew;
    }

    float inv = 1.f / l;
    float* op = out + ((size_t)(b * Sq + qi) * Dm + h * HDIM);
    #pragma unroll
    for (int d = 0; d < HDIM; d += 4) {
        float4 t;
        t.x = o[d] * inv; t.y = o[d+1] * inv;
        t.z = o[d+2] * inv; t.w = o[d+3] * inv;
        *(float4*)(op + d) = t;
    }
}

// ------------------------- LayerNorm(a + b) --------------------------------
__global__ __launch_bounds__(256)
void ln_kernel(const float* __restrict__ a, const float* __restrict__ bsrc,
               const float* __restrict__ g, const float* __restrict__ beta,
               float* __restrict__ out)
{
    const int row = blockIdx.x;
    __shared__ float buf[Dm];
    __shared__ float red[8];
    const int tid = threadIdx.x;
    const int lane = tid & 31, wid = tid >> 5;

    float s = 0.f;
    for (int d = tid; d < Dm; d += 256) {
        float v = a[(size_t)row * Dm + d] + bsrc[(size_t)row * Dm + d];
        buf[d] = v;
        s += v;
    }
    #pragma unroll
    for (int o = 16; o; o >>= 1) s += __shfl_xor_sync(0xffffffffu, s, o);
    if (lane == 0) red[wid] = s;
    __syncthreads();
    float mean = (red[0]+red[1]+red[2]+red[3]+red[4]+red[5]+red[6]+red[7]) * (1.f/Dm);

    float s2 = 0.f;
    for (int d = tid; d < Dm; d += 256) {
        float c = buf[d] - mean;
        s2 += c * c;
    }
    #pragma unroll
    for (int o = 16; o; o >>= 1) s2 += __shfl_xor_sync(0xffffffffu, s2, o);
    __syncthreads();
    if (lane == 0) red[wid] = s2;
    __syncthreads();
    float var = (red[0]+red[1]+red[2]+red[3]+red[4]+red[5]+red[6]+red[7]) * (1.f/Dm);
    float rstd = rsqrtf(var + 1e-5f);

    for (int d = tid; d < Dm; d += 256)
        out[(size_t)row * Dm + d] = (buf[d] - mean) * rstd * g[d] + beta[d];
}

// ------------------------- gating + top-2 routing --------------------------
__global__ __launch_bounds__(128)
void gate_kernel(const float* __restrict__ x1, const float* __restrict__ gW,
                 const float* __restrict__ gb, int* __restrict__ cnt,
                 int* __restrict__ tokl, float* __restrict__ wtl,
                 float* __restrict__ gsum)
{
    const int t = blockIdx.x;
    __shared__ float xs[Dm];
    __shared__ float lg[Ee];
    const int tid = threadIdx.x;
    for (int d = tid; d < Dm; d += 128) xs[d] = x1[(size_t)t * Dm + d];
    __syncthreads();

    const int lane = tid & 31, wid = tid >> 5;
    for (int e = wid; e < Ee; e += 4) {
        float s = 0.f;
        for (int d = lane; d < Dm; d += 32) s += xs[d] * gW[d * Ee + e];
        #pragma unroll
        for (int o = 16; o; o >>= 1) s += __shfl_xor_sync(0xffffffffu, s, o);
        if (lane == 0) lg[e] = s + gb[e];
    }
    __syncthreads();

    if (tid == 0) {
        float mx = lg[0];
        #pragma unroll
        for (int e = 1; e < Ee; e++) mx = fmaxf(mx, lg[e]);
        float sc[Ee];
        float se = 0.f;
        #pragma unroll
        for (int e = 0; e < Ee; e++) { sc[e] = expf(lg[e] - mx); se += sc[e]; }
        float inv = 1.f / se;
        #pragma unroll
        for (int e = 0; e < Ee; e++) sc[e] *= inv;

        int i1 = 0;
        #pragma unroll
        for (int e = 1; e < Ee; e++) if (sc[e] > sc[i1]) i1 = e;
        int i2 = (i1 == 0) ? 1 : 0;
        #pragma unroll
        for (int e = 0; e < Ee; e++) { if (e == i1 || e == i2) continue; if (sc[e] > sc[i2]) i2 = e; }

        float ws = sc[i1] + sc[i2];
        float w1 = sc[i1] / ws, w2 = sc[i2] / ws;
        int p1 = atomicAdd(&cnt[i1], 1); tokl[i1 * Tt + p1] = t; wtl[i1 * Tt + p1] = w1;
        int p2 = atomicAdd(&cnt[i2], 1); tokl[i2 * Tt + p2] = t; wtl[i2 * Tt + p2] = w2;
        #pragma unroll
        for (int e = 0; e < Ee; e++) atomicAdd(&gsum[e], sc[e]);
    }
}

// ------------------------- small helpers -----------------------------------
__global__ void zero_kernel(float* moe, int* cnt, float* gsum)
{
    int i = blockIdx.x * blockDim.x + threadIdx.x;
    int stride = gridDim.x * blockDim.x;
    for (int j = i; j < Tt * Dm; j += stride) moe[j] = 0.f;
    if (i < Ee) { cnt[i] = 0; gsum[i] = 0.f; }
}

__global__ void offsets_kernel(const int* cnt, int* off)
{
    if (threadIdx.x == 0) {
        int s = 0;
        for (int e = 0; e < Ee; e++) { off[e] = s; s += cnt[e]; }
    }
}

__global__ void aux_kernel(const int* cnt, const float* gsum, float* dst)
{
    if (threadIdx.x == 0) {
        float a = 0.f;
        for (int e = 0; e < Ee; e++)
            a += ((float)cnt[e] / (float)(Tt * Kk)) * (gsum[e] / (float)Tt);
        dst[0] = (float)Ee * a;
    }
}

// ------------------------- launch ------------------------------------------
extern "C" void kernel_launch(void* const* d_in, const int* in_sizes, int n_in,
                              void* d_out, int out_size)
{
    const float* x     = (const float*)d_in[0];
    const float* Wq    = (const float*)d_in[1];
    const float* bq    = (const float*)d_in[2];
    const float* Wk    = (const float*)d_in[3];
    const float* bk    = (const float*)d_in[4];
    const float* Wv    = (const float*)d_in[5];
    const float* bv    = (const float*)d_in[6];
    const float* Wo    = (const float*)d_in[7];
    const float* bo    = (const float*)d_in[8];
    const float* g1    = (const float*)d_in[9];
    const float* beta1 = (const float*)d_in[10];
    const float* gateW = (const float*)d_in[11];
    const float* gateb = (const float*)d_in[12];
    const float* eW1   = (const float*)d_in[13];
    const float* eb1   = (const float*)d_in[14];
    const float* eW2   = (const float*)d_in[15];
    const float* eb2   = (const float*)d_in[16];
    const float* g2    = (const float*)d_in[17];
    const float* beta2 = (const float*)d_in[18];
    float* out = (float*)d_out;

    float *pq, *pk, *pv, *pat, *ppr, *px1, *pmoe, *ph, *pwt, *pgs;
    int *ptok, *pcnt, *poff;
    cudaGetSymbolAddress((void**)&pq,   g_q);
    cudaGetSymbolAddress((void**)&pk,   g_k);
    cudaGetSymbolAddress((void**)&pv,   g_v);
    cudaGetSymbolAddress((void**)&pat,  g_att);
    cudaGetSymbolAddress((void**)&ppr,  g_prj);
    cudaGetSymbolAddress((void**)&px1,  g_x1);
    cudaGetSymbolAddress((void**)&pmoe, g_moe);
    cudaGetSymbolAddress((void**)&ph,   g_h);
    cudaGetSymbolAddress((void**)&ptok, g_tok);
    cudaGetSymbolAddress((void**)&pwt,  g_wt);
    cudaGetSymbolAddress((void**)&pcnt, g_cnt);
    cudaGetSymbolAddress((void**)&poff, g_off);
    cudaGetSymbolAddress((void**)&pgs,  g_gsum);

    dim3 gQ(Dm / 128, Tt / 128, 1);   // (8, 64)

    // QKV projections
    gemm_kernel<0><<<gQ, 256>>>(x, Wq, bq, pq, Tt, Dm, Dm, nullptr, nullptr, nullptr, nullptr);
    gemm_kernel<0><<<gQ, 256>>>(x, Wk, bk, pk, Tt, Dm, Dm, nullptr, nullptr, nullptr, nullptr);
    gemm_kernel<0><<<gQ, 256>>>(x, Wv, bv, pv, Tt, Dm, Dm, nullptr, nullptr, nullptr, nullptr);

    // attention
    attn_kernel<<<dim3(Sq / 128, Bc * Hh), 128>>>(pq, pk, pv, pat);

    // output projection + residual LN1
    gemm_kernel<0><<<gQ, 256>>>(pat, Wo, bo, ppr, Tt, Dm, Dm, nullptr, nullptr, nullptr, nullptr);
    ln_kernel<<<Tt, 256>>>(x, ppr, g1, beta1, px1);

    // MoE: routing + sparse expert GEMMs
    zero_kernel<<<2048, 256>>>(pmoe, pcnt, pgs);
    gate_kernel<<<Tt, 128>>>(px1, gateW, gateb, pcnt, ptok, pwt, pgs);
    offsets_kernel<<<1, 32>>>(pcnt, poff);
    gemm_kernel<1><<<dim3(Ff / 128, Tt / 128, Ee), 256>>>(
        px1, eW1, eb1, ph, Tt, Ff, Dm, pcnt, poff, ptok, pwt);
    gemm_kernel<2><<<dim3(Dm / 128, Tt / 128, Ee), 256>>>(
        ph, eW2, eb2, pmoe, Tt, Dm, Ff, pcnt, poff, ptok, pwt);

    // final residual LN2 -> output
    ln_kernel<<<Tt, 256>>>(px1, pmoe, g2, beta2, out);

    // aux loss scalar appended after the [B,S,D] tensor
    if (out_size > Tt * Dm)
        aux_kernel<<<1, 32>>>(pcnt, pgs, out + (size_t)Tt * Dm);
}

// round 7
// speedup vs baseline: 1.6922x; 1.6922x over previous
#include <cuda_runtime.h>
#include <math.h>
#include <stdint.h>

#define Bc 4
#define Sq 2048
#define Dm 1024
#define Hh 16
#define HDIM 64
#define Ff 4096
#define Ee 8
#define Kk 2
#define Tt (Bc*Sq)   /* 8192 tokens */

// ------------------------- scratch (device globals; no allocs allowed) ----
__device__ float g_q  [(size_t)Tt*Dm];
__device__ float g_k  [(size_t)Tt*Dm];
__device__ float g_v  [(size_t)Tt*Dm];
__device__ float g_att[(size_t)Tt*Dm];
__device__ float g_prj[(size_t)Tt*Dm];
__device__ float g_x1 [(size_t)Tt*Dm];
__device__ float g_moe[(size_t)Tt*Dm];
__device__ float g_h  [(size_t)Tt*Kk*Ff];     // packed expert hidden (16384 x 4096)
__device__ int   g_tok[Ee*Tt];
__device__ float g_wt [Ee*Tt];
__device__ int   g_cnt[Ee];
__device__ int   g_off[Ee];
__device__ float g_gsum[Ee];

// ------------------------- helpers -----------------------------------------
// Split two fp32 values (x0 -> low half, x1 -> high half) into bf16x2 hi and
// bf16x2 lo such that x ~= hi + lo to ~16 mantissa bits.
__device__ __forceinline__ void split2(float x0, float x1,
                                       uint32_t& hi, uint32_t& lo)
{
    uint32_t h;
    asm("cvt.rn.bf16x2.f32 %0, %1, %2;" : "=r"(h) : "f"(x1), "f"(x0));
    float h0 = __uint_as_float(h << 16);
    float h1 = __uint_as_float(h & 0xffff0000u);
    uint32_t l;
    asm("cvt.rn.bf16x2.f32 %0, %1, %2;" : "=r"(l) : "f"(x1 - h1), "f"(x0 - h0));
    hi = h; lo = l;
}

__device__ __forceinline__ void mma_bf16(float c[4],
    uint32_t a0, uint32_t a1, uint32_t a2, uint32_t a3,
    uint32_t b0, uint32_t b1)
{
    asm volatile(
        "mma.sync.aligned.m16n8k16.row.col.f32.bf16.bf16.f32 "
        "{%0,%1,%2,%3}, {%4,%5,%6,%7}, {%8,%9}, {%0,%1,%2,%3};"
        : "+f"(c[0]), "+f"(c[1]), "+f"(c[2]), "+f"(c[3])
        : "r"(a0), "r"(a1), "r"(a2), "r"(a3), "r"(b0), "r"(b1));
}

#define CP_ASYNC16(dst, src) \
    asm volatile("cp.async.cg.shared.global [%0], [%1], 16;" :: "r"(dst), "l"(src))
#define CP_COMMIT() asm volatile("cp.async.commit_group;")

// ------------------------- bf16x3 tensor-core GEMM -------------------------
// 128x128 tile, BK=16, 256 threads (8 warps, each 64x32), double-buffered
// cp.async, fp32 smem tiles, per-fragment bf16 hi/lo decomposition,
// 3 MMAs (hh, hl, lh) per fragment pair -> ~fp32 accuracy.
// MODE 0: C = A@B + bias. MODE 1: gathered rows + GELU -> packed h.
// MODE 2: packed h @ W2, scatter-add w*(acc+bias) into moe[token].
#define APITCH 20
#define BPITCH 136

template<int MODE>
__global__ __launch_bounds__(256, 2)
void gemm_tc(const float* __restrict__ A,
             const float* __restrict__ Bm,
             const float* __restrict__ bias,
             float* __restrict__ C,
             int M, int N, int Kd,
             const int* __restrict__ cnt,
             const int* __restrict__ off,
             const int* __restrict__ tokl,
             const float* __restrict__ wtl)
{
    const int e  = blockIdx.z;
    const int m0 = blockIdx.y * 128;
    const int n0 = blockIdx.x * 128;

    int Me = M, hbase = 0;
    const float* Bp = Bm;
    const float* bp = bias;
    if (MODE != 0) {
        Me = cnt[e];
        if (m0 >= Me) return;
        Bp = Bm + (size_t)e * Kd * N;
        bp = bias + (size_t)e * N;
        hbase = off[e];
    }

    __shared__ float As[2][128][APITCH];
    __shared__ float Bs[2][16][BPITCH];

    const int tid  = threadIdx.x;
    const int lane = tid & 31, warp = tid >> 5;
    const int wm = warp >> 2, wn = warp & 3;     // 2 x 4 warp grid
    const int tr = lane >> 2, tc = lane & 3;

    // ---- global->smem load mapping ----
    const int ra = tid >> 1;            // A tile row 0..127
    const int ka = (tid & 1) * 8;       // A k offset {0,8}
    const float* Arow;
    {
        int ar = m0 + ra;
        if (MODE == 0) {
            Arow = A + (size_t)ar * Kd;
        } else {
            int idx = ar < Me ? ar : Me - 1;   // clamp (epilogue masks)
            if (MODE == 1) Arow = A + (size_t)tokl[e * Tt + idx] * Kd;
            else           Arow = A + (size_t)(hbase + idx) * Kd;
        }
    }
    const int rb = tid >> 5;            // B tile rows rb, rb+8
    const int cb = (tid & 31) * 4;      // B tile col

    uint32_t sA = (uint32_t)__cvta_generic_to_shared(&As[0][0][0]);
    uint32_t sB = (uint32_t)__cvta_generic_to_shared(&Bs[0][0][0]);
    const uint32_t dA = sA + (uint32_t)(ra * APITCH + ka) * 4;
    const uint32_t dB = sB + (uint32_t)(rb * BPITCH + cb) * 4;
    const uint32_t stageA = 128 * APITCH * 4;
    const uint32_t stageB = 16 * BPITCH * 4;

    float acc[4][4][4];
    #pragma unroll
    for (int i = 0; i < 4; i++)
        #pragma unroll
        for (int j = 0; j < 4; j++)
            #pragma unroll
            for (int q = 0; q < 4; q++) acc[i][j][q] = 0.f;

    const int ktiles = Kd / 16;

    // prologue: stage 0
    {
        CP_ASYNC16(dA, Arow + ka);
        CP_ASYNC16(dA + 16, Arow + ka + 4);
        CP_ASYNC16(dB, Bp + (size_t)rb * N + n0 + cb);
        CP_ASYNC16(dB + BPITCH * 8 * 4, Bp + (size_t)(rb + 8) * N + n0 + cb);
        CP_COMMIT();
    }

    for (int t = 0; t < ktiles; t++) {
        const int cur = t & 1;
        if (t + 1 < ktiles) {
            const int nxt = (t + 1) & 1;
            const int k0 = (t + 1) * 16;
            CP_ASYNC16(dA + nxt * stageA, Arow + k0 + ka);
            CP_ASYNC16(dA + nxt * stageA + 16, Arow + k0 + ka + 4);
            CP_ASYNC16(dB + nxt * stageB, Bp + (size_t)(k0 + rb) * N + n0 + cb);
            CP_ASYNC16(dB + nxt * stageB + BPITCH * 8 * 4,
                       Bp + (size_t)(k0 + rb + 8) * N + n0 + cb);
            CP_COMMIT();
            asm volatile("cp.async.wait_group 1;");
        } else {
            asm volatile("cp.async.wait_group 0;");
        }
        __syncthreads();

        const float (*Ab)[APITCH] = As[cur];
        const float (*Bb)[BPITCH] = Bs[cur];

        // ---- A fragments for the whole k16 tile (hi/lo split once) ----
        uint32_t ah[4][4], al[4][4];
        #pragma unroll
        for (int i = 0; i < 4; i++) {
            const float* p = &Ab[wm * 64 + i * 16 + tr][2 * tc];
            float2 x = *(const float2*)p;                       // (row,   k0..1)
            float2 y = *(const float2*)(p + 8 * APITCH);        // (row+8, k0..1)
            float2 z = *(const float2*)(p + 8);                 // (row,   k8..9)
            float2 w = *(const float2*)(p + 8 * APITCH + 8);    // (row+8, k8..9)
            split2(x.x, x.y, ah[i][0], al[i][0]);
            split2(y.x, y.y, ah[i][1], al[i][1]);
            split2(z.x, z.y, ah[i][2], al[i][2]);
            split2(w.x, w.y, ah[i][3], al[i][3]);
        }

        // ---- stream B fragments, 3 MMAs each (hh, hl, lh) ----
        #pragma unroll
        for (int j = 0; j < 4; j++) {
            const int n = wn * 32 + j * 8 + tr;
            uint32_t b0h, b0l, b1h, b1l;
            split2(Bb[2 * tc][n],     Bb[2 * tc + 1][n],     b0h, b0l);
            split2(Bb[8 + 2 * tc][n], Bb[8 + 2 * tc + 1][n], b1h, b1l);
            #pragma unroll
            for (int i = 0; i < 4; i++) {
                mma_bf16(acc[i][j], ah[i][0], ah[i][1], ah[i][2], ah[i][3], b0h, b1h);
                mma_bf16(acc[i][j], ah[i][0], ah[i][1], ah[i][2], ah[i][3], b0l, b1l);
                mma_bf16(acc[i][j], al[i][0], al[i][1], al[i][2], al[i][3], b0h, b1h);
            }
        }
        __syncthreads();
    }

    // ---- epilogue ----
    #pragma unroll
    for (int i = 0; i < 4; i++) {
        const int r = m0 + wm * 64 + i * 16 + tr;   // rows r and r+8
        #pragma unroll
        for (int j = 0; j < 4; j++) {
            const int c = n0 + wn * 32 + j * 8 + tc * 2;
            const float b0 = bp[c], b1 = bp[c + 1];
            if (MODE == 0) {
                float2 v0 = make_float2(acc[i][j][0] + b0, acc[i][j][1] + b1);
                float2 v1 = make_float2(acc[i][j][2] + b0, acc[i][j][3] + b1);
                *(float2*)&C[(size_t)r * N + c] = v0;
                *(float2*)&C[(size_t)(r + 8) * N + c] = v1;
            } else if (MODE == 1) {
                if (r < Me) {
                    float v0 = acc[i][j][0] + b0, v1 = acc[i][j][1] + b1;
                    float2 o;
                    o.x = 0.5f * v0 * (1.0f + erff(v0 * 0.7071067811865475f));
                    o.y = 0.5f * v1 * (1.0f + erff(v1 * 0.7071067811865475f));
                    *(float2*)&C[(size_t)(hbase + r) * N + c] = o;
                }
                if (r + 8 < Me) {
                    float v0 = acc[i][j][2] + b0, v1 = acc[i][j][3] + b1;
                    float2 o;
                    o.x = 0.5f * v0 * (1.0f + erff(v0 * 0.7071067811865475f));
                    o.y = 0.5f * v1 * (1.0f + erff(v1 * 0.7071067811865475f));
                    *(float2*)&C[(size_t)(hbase + r + 8) * N + c] = o;
                }
            } else {
                if (r < Me) {
                    int   tk = tokl[e * Tt + r];
                    float w  = wtl [e * Tt + r];
                    float* Crow = &C[(size_t)tk * N + c];
                    atomicAdd(&Crow[0], w * (acc[i][j][0] + b0));
                    atomicAdd(&Crow[1], w * (acc[i][j][1] + b1));
                }
                if (r + 8 < Me) {
                    int   tk = tokl[e * Tt + r + 8];
                    float w  = wtl [e * Tt + r + 8];
                    float* Crow = &C[(size_t)tk * N + c];
                    atomicAdd(&Crow[0], w * (acc[i][j][2] + b0));
                    atomicAdd(&Crow[1], w * (acc[i][j][3] + b1));
                }
            }
        }
    }
}

// ------------------------- flash attention ---------------------------------
__global__ __launch_bounds__(128, 2)
void attn_kernel(const float* __restrict__ q, const float* __restrict__ k,
                 const float* __restrict__ v, float* __restrict__ out)
{
    const int bh = blockIdx.y;
    const int b = bh >> 4, h = bh & 15;
    const int qi = blockIdx.x * 128 + threadIdx.x;

    const float* qp = q + ((size_t)(b * Sq + qi) * Dm + h * HDIM);
    float qr[HDIM];
    #pragma unroll
    for (int d = 0; d < HDIM; d += 4) {
        float4 t = *(const float4*)(qp + d);
        qr[d] = t.x * 0.125f; qr[d+1] = t.y * 0.125f;
        qr[d+2] = t.z * 0.125f; qr[d+3] = t.w * 0.125f;
    }
    float o[HDIM];
    #pragma unroll
    for (int d = 0; d < HDIM; d++) o[d] = 0.f;
    float m = -1e30f, l = 0.f;

    __shared__ float Ks[64][HDIM];
    __shared__ float Vs[64][HDIM];

    for (int t0 = 0; t0 < Sq; t0 += 64) {
        __syncthreads();
        for (int i = threadIdx.x; i < 64 * (HDIM / 4); i += 128) {
            int r = i >> 4;
            int c = (i & 15) * 4;
            size_t base = (size_t)(b * Sq + t0 + r) * Dm + h * HDIM + c;
            *(float4*)&Ks[r][c] = *(const float4*)(k + base);
            *(float4*)&Vs[r][c] = *(const float4*)(v + base);
        }
        __syncthreads();

        float s[64];
        #pragma unroll 4
        for (int j = 0; j < 64; j++) {
            float a0 = 0.f, a1 = 0.f, a2 = 0.f, a3 = 0.f;
            #pragma unroll
            for (int d = 0; d < HDIM; d += 4) {
                float4 kv = *(const float4*)&Ks[j][d];
                a0 += qr[d]   * kv.x;  a1 += qr[d+1] * kv.y;
                a2 += qr[d+2] * kv.z;  a3 += qr[d+3] * kv.w;
            }
            s[j] = (a0 + a1) + (a2 + a3);
        }
        float mt = s[0];
        #pragma unroll 8
        for (int j = 1; j < 64; j++) mt = fmaxf(mt, s[j]);
        float mnew = fmaxf(m, mt);
        float alpha = __expf(m - mnew);
        l *= alpha;
        #pragma unroll
        for (int d = 0; d < HDIM; d++) o[d] *= alpha;

        #pragma unroll 2
        for (int j = 0; j < 64; j++) {
            float p = __expf(s[j] - mnew);
            l += p;
            #pragma unroll
            for (int d = 0; d < HDIM; d += 4) {
                float4 vv = *(const float4*)&Vs[j][d];
                o[d]   += p * vv.x;  o[d+1] += p * vv.y;
                o[d+2] += p * vv.z;  o[d+3] += p * vv.w;
            }
        }
        m = mnew;
    }

    float inv = 1.f / l;
    float* op = out + ((size_t)(b * Sq + qi) * Dm + h * HDIM);
    #pragma unroll
    for (int d = 0; d < HDIM; d += 4) {
        float4 t;
        t.x = o[d] * inv; t.y = o[d+1] * inv;
        t.z = o[d+2] * inv; t.w = o[d+3] * inv;
        *(float4*)(op + d) = t;
    }
}

// ------------------------- LayerNorm(a + b) --------------------------------
__global__ __launch_bounds__(256)
void ln_kernel(const float* __restrict__ a, const float* __restrict__ bsrc,
               const float* __restrict__ g, const float* __restrict__ beta,
               float* __restrict__ out)
{
    const int row = blockIdx.x;
    __shared__ float buf[Dm];
    __shared__ float red[8];
    const int tid = threadIdx.x;
    const int lane = tid & 31, wid = tid >> 5;

    float s = 0.f;
    for (int d = tid; d < Dm; d += 256) {
        float v = a[(size_t)row * Dm + d] + bsrc[(size_t)row * Dm + d];
        buf[d] = v;
        s += v;
    }
    #pragma unroll
    for (int o = 16; o; o >>= 1) s += __shfl_xor_sync(0xffffffffu, s, o);
    if (lane == 0) red[wid] = s;
    __syncthreads();
    float mean = (red[0]+red[1]+red[2]+red[3]+red[4]+red[5]+red[6]+red[7]) * (1.f/Dm);

    float s2 = 0.f;
    for (int d = tid; d < Dm; d += 256) {
        float c = buf[d] - mean;
        s2 += c * c;
    }
    #pragma unroll
    for (int o = 16; o; o >>= 1) s2 += __shfl_xor_sync(0xffffffffu, s2, o);
    __syncthreads();
    if (lane == 0) red[wid] = s2;
    __syncthreads();
    float var = (red[0]+red[1]+red[2]+red[3]+red[4]+red[5]+red[6]+red[7]) * (1.f/Dm);
    float rstd = rsqrtf(var + 1e-5f);

    for (int d = tid; d < Dm; d += 256)
        out[(size_t)row * Dm + d] = (buf[d] - mean) * rstd * g[d] + beta[d];
}

// ------------------------- gating + top-2 routing --------------------------
__global__ __launch_bounds__(128)
void gate_kernel(const float* __restrict__ x1, const float* __restrict__ gW,
                 const float* __restrict__ gb, int* __restrict__ cnt,
                 int* __restrict__ tokl, float* __restrict__ wtl,
                 float* __restrict__ gsum)
{
    const int t = blockIdx.x;
    __shared__ float xs[Dm];
    __shared__ float lg[Ee];
    const int tid = threadIdx.x;
    for (int d = tid; d < Dm; d += 128) xs[d] = x1[(size_t)t * Dm + d];
    __syncthreads();

    const int lane = tid & 31, wid = tid >> 5;
    for (int e = wid; e < Ee; e += 4) {
        float s = 0.f;
        for (int d = lane; d < Dm; d += 32) s += xs[d] * gW[d * Ee + e];
        #pragma unroll
        for (int o = 16; o; o >>= 1) s += __shfl_xor_sync(0xffffffffu, s, o);
        if (lane == 0) lg[e] = s + gb[e];
    }
    __syncthreads();

    if (tid == 0) {
        float mx = lg[0];
        #pragma unroll
        for (int e = 1; e < Ee; e++) mx = fmaxf(mx, lg[e]);
        float sc[Ee];
        float se = 0.f;
        #pragma unroll
        for (int e = 0; e < Ee; e++) { sc[e] = expf(lg[e] - mx); se += sc[e]; }
        float inv = 1.f / se;
        #pragma unroll
        for (int e = 0; e < Ee; e++) sc[e] *= inv;

        int i1 = 0;
        #pragma unroll
        for (int e = 1; e < Ee; e++) if (sc[e] > sc[i1]) i1 = e;
        int i2 = (i1 == 0) ? 1 : 0;
        #pragma unroll
        for (int e = 0; e < Ee; e++) { if (e == i1 || e == i2) continue; if (sc[e] > sc[i2]) i2 = e; }

        float ws = sc[i1] + sc[i2];
        float w1 = sc[i1] / ws, w2 = sc[i2] / ws;
        int p1 = atomicAdd(&cnt[i1], 1); tokl[i1 * Tt + p1] = t; wtl[i1 * Tt + p1] = w1;
        int p2 = atomicAdd(&cnt[i2], 1); tokl[i2 * Tt + p2] = t; wtl[i2 * Tt + p2] = w2;
        #pragma unroll
        for (int e = 0; e < Ee; e++) atomicAdd(&gsum[e], sc[e]);
    }
}

// ------------------------- small helpers -----------------------------------
__global__ void zero_kernel(float* moe, int* cnt, float* gsum)
{
    int i = blockIdx.x * blockDim.x + threadIdx.x;
    int stride = gridDim.x * blockDim.x;
    for (int j = i; j < Tt * Dm; j += stride) moe[j] = 0.f;
    if (i < Ee) { cnt[i] = 0; gsum[i] = 0.f; }
}

__global__ void offsets_kernel(const int* cnt, int* off)
{
    if (threadIdx.x == 0) {
        int s = 0;
        for (int e = 0; e < Ee; e++) { off[e] = s; s += cnt[e]; }
    }
}

__global__ void aux_kernel(const int* cnt, const float* gsum, float* dst)
{
    if (threadIdx.x == 0) {
        float a = 0.f;
        for (int e = 0; e < Ee; e++)
            a += ((float)cnt[e] / (float)(Tt * Kk)) * (gsum[e] / (float)Tt);
        dst[0] = (float)Ee * a;
    }
}

// ------------------------- launch ------------------------------------------
extern "C" void kernel_launch(void* const* d_in, const int* in_sizes, int n_in,
                              void* d_out, int out_size)
{
    const float* x     = (const float*)d_in[0];
    const float* Wq    = (const float*)d_in[1];
    const float* bq    = (const float*)d_in[2];
    const float* Wk    = (const float*)d_in[3];
    const float* bk    = (const float*)d_in[4];
    const float* Wv    = (const float*)d_in[5];
    const float* bv    = (const float*)d_in[6];
    const float* Wo    = (const float*)d_in[7];
    const float* bo    = (const float*)d_in[8];
    const float* g1    = (const float*)d_in[9];
    const float* beta1 = (const float*)d_in[10];
    const float* gateW = (const float*)d_in[11];
    const float* gateb = (const float*)d_in[12];
    const float* eW1   = (const float*)d_in[13];
    const float* eb1   = (const float*)d_in[14];
    const float* eW2   = (const float*)d_in[15];
    const float* eb2   = (const float*)d_in[16];
    const float* g2    = (const float*)d_in[17];
    const float* beta2 = (const float*)d_in[18];
    float* out = (float*)d_out;

    float *pq, *pk, *pv, *pat, *ppr, *px1, *pmoe, *ph, *pwt, *pgs;
    int *ptok, *pcnt, *poff;
    cudaGetSymbolAddress((void**)&pq,   g_q);
    cudaGetSymbolAddress((void**)&pk,   g_k);
    cudaGetSymbolAddress((void**)&pv,   g_v);
    cudaGetSymbolAddress((void**)&pat,  g_att);
    cudaGetSymbolAddress((void**)&ppr,  g_prj);
    cudaGetSymbolAddress((void**)&px1,  g_x1);
    cudaGetSymbolAddress((void**)&pmoe, g_moe);
    cudaGetSymbolAddress((void**)&ph,   g_h);
    cudaGetSymbolAddress((void**)&ptok, g_tok);
    cudaGetSymbolAddress((void**)&pwt,  g_wt);
    cudaGetSymbolAddress((void**)&pcnt, g_cnt);
    cudaGetSymbolAddress((void**)&poff, g_off);
    cudaGetSymbolAddress((void**)&pgs,  g_gsum);

    dim3 gQ(Dm / 128, Tt / 128, 1);   // (8, 64)

    // QKV projections (bf16x3 tensor cores)
    gemm_tc<0><<<gQ, 256>>>(x, Wq, bq, pq, Tt, Dm, Dm, nullptr, nullptr, nullptr, nullptr);
    gemm_tc<0><<<gQ, 256>>>(x, Wk, bk, pk, Tt, Dm, Dm, nullptr, nullptr, nullptr, nullptr);
    gemm_tc<0><<<gQ, 256>>>(x, Wv, bv, pv, Tt, Dm, Dm, nullptr, nullptr, nullptr, nullptr);

    // attention
    attn_kernel<<<dim3(Sq / 128, Bc * Hh), 128>>>(pq, pk, pv, pat);

    // output projection + residual LN1
    gemm_tc<0><<<gQ, 256>>>(pat, Wo, bo, ppr, Tt, Dm, Dm, nullptr, nullptr, nullptr, nullptr);
    ln_kernel<<<Tt, 256>>>(x, ppr, g1, beta1, px1);

    // MoE: routing + sparse expert GEMMs
    zero_kernel<<<2048, 256>>>(pmoe, pcnt, pgs);
    gate_kernel<<<Tt, 128>>>(px1, gateW, gateb, pcnt, ptok, pwt, pgs);
    offsets_kernel<<<1, 32>>>(pcnt, poff);
    gemm_tc<1><<<dim3(Ff / 128, Tt / 128, Ee), 256>>>(
        px1, eW1, eb1, ph, Tt, Ff, Dm, pcnt, poff, ptok, pwt);
    gemm_tc<2><<<dim3(Dm / 128, Tt / 128, Ee), 256>>>(
        ph, eW2, eb2, pmoe, Tt, Dm, Ff, pcnt, poff, ptok, pwt);

    // final residual LN2 -> output
    ln_kernel<<<Tt, 256>>>(px1, pmoe, g2, beta2, out);

    // aux loss scalar appended after the [B,S,D] tensor
    if (out_size > Tt * Dm)
        aux_kernel<<<1, 32>>>(pcnt, pgs, out + (size_t)Tt * Dm);
}

// round 9
// speedup vs baseline: 2.3280x; 1.3757x over previous
#include <cuda_runtime.h>
#include <math.h>
#include <stdint.h>

#define Bc 4
#define Sq 2048
#define Dm 1024
#define Hh 16
#define HDIM 64
#define Ff 4096
#define Ee 8
#define Kk 2
#define Tt (Bc*Sq)   /* 8192 tokens */

// ------------------------- scratch (device globals; no allocs allowed) ----
__device__ float g_q  [(size_t)Tt*Dm];
__device__ float g_k  [(size_t)Tt*Dm];
__device__ float g_v  [(size_t)Tt*Dm];
__device__ float g_att[(size_t)Tt*Dm];
__device__ float g_prj[(size_t)Tt*Dm];
__device__ float g_x1 [(size_t)Tt*Dm];
__device__ float g_moe[(size_t)Tt*Dm];
__device__ float g_h  [(size_t)Tt*Kk*Ff];     // packed expert hidden (16384 x 4096)
__device__ int   g_tok[Ee*Tt];
__device__ float g_wt [Ee*Tt];
__device__ int   g_cnt[Ee];
__device__ int   g_off[Ee];
__device__ float g_gsum[Ee];

// ------------------------- helpers -----------------------------------------
// Split two fp32 values (x0 -> low half, x1 -> high half) into bf16x2 hi and
// bf16x2 lo such that x ~= hi + lo to ~16 mantissa bits.
__device__ __forceinline__ void split2(float x0, float x1,
                                       uint32_t& hi, uint32_t& lo)
{
    uint32_t h;
    asm("cvt.rn.bf16x2.f32 %0, %1, %2;" : "=r"(h) : "f"(x1), "f"(x0));
    float h0 = __uint_as_float(h << 16);
    float h1 = __uint_as_float(h & 0xffff0000u);
    uint32_t l;
    asm("cvt.rn.bf16x2.f32 %0, %1, %2;" : "=r"(l) : "f"(x1 - h1), "f"(x0 - h0));
    hi = h; lo = l;
}

__device__ __forceinline__ void mma_bf16(float c[4],
    uint32_t a0, uint32_t a1, uint32_t a2, uint32_t a3,
    uint32_t b0, uint32_t b1)
{
    asm volatile(
        "mma.sync.aligned.m16n8k16.row.col.f32.bf16.bf16.f32 "
        "{%0,%1,%2,%3}, {%4,%5,%6,%7}, {%8,%9}, {%0,%1,%2,%3};"
        : "+f"(c[0]), "+f"(c[1]), "+f"(c[2]), "+f"(c[3])
        : "r"(a0), "r"(a1), "r"(a2), "r"(a3), "r"(b0), "r"(b1));
}

#define CP_ASYNC16(dst, src) \
    asm volatile("cp.async.cg.shared.global [%0], [%1], 16;" :: "r"(dst), "l"(src))
#define CP_COMMIT() asm volatile("cp.async.commit_group;")

// ------------------------- bf16x3 tensor-core GEMM -------------------------
#define APITCH 20
#define BPITCH 136

template<int MODE>
__global__ __launch_bounds__(256, 2)
void gemm_tc(const float* __restrict__ A,
             const float* __restrict__ Bm,
             const float* __restrict__ bias,
             float* __restrict__ C,
             int M, int N, int Kd,
             const int* __restrict__ cnt,
             const int* __restrict__ off,
             const int* __restrict__ tokl,
             const float* __restrict__ wtl)
{
    const int e  = blockIdx.z;
    const int m0 = blockIdx.y * 128;
    const int n0 = blockIdx.x * 128;

    int Me = M, hbase = 0;
    const float* Bp = Bm;
    const float* bp = bias;
    if (MODE != 0) {
        Me = cnt[e];
        if (m0 >= Me) return;
        Bp = Bm + (size_t)e * Kd * N;
        bp = bias + (size_t)e * N;
        hbase = off[e];
    }

    __shared__ float As[2][128][APITCH];
    __shared__ float Bs[2][16][BPITCH];

    const int tid  = threadIdx.x;
    const int lane = tid & 31, warp = tid >> 5;
    const int wm = warp >> 2, wn = warp & 3;     // 2 x 4 warp grid
    const int tr = lane >> 2, tc = lane & 3;

    const int ra = tid >> 1;            // A tile row 0..127
    const int ka = (tid & 1) * 8;       // A k offset {0,8}
    const float* Arow;
    {
        int ar = m0 + ra;
        if (MODE == 0) {
            Arow = A + (size_t)ar * Kd;
        } else {
            int idx = ar < Me ? ar : Me - 1;   // clamp (epilogue masks)
            if (MODE == 1) Arow = A + (size_t)tokl[e * Tt + idx] * Kd;
            else           Arow = A + (size_t)(hbase + idx) * Kd;
        }
    }
    const int rb = tid >> 5;            // B tile rows rb, rb+8
    const int cb = (tid & 31) * 4;      // B tile col

    uint32_t sA = (uint32_t)__cvta_generic_to_shared(&As[0][0][0]);
    uint32_t sB = (uint32_t)__cvta_generic_to_shared(&Bs[0][0][0]);
    const uint32_t dA = sA + (uint32_t)(ra * APITCH + ka) * 4;
    const uint32_t dB = sB + (uint32_t)(rb * BPITCH + cb) * 4;
    const uint32_t stageA = 128 * APITCH * 4;
    const uint32_t stageB = 16 * BPITCH * 4;

    float acc[4][4][4];
    #pragma unroll
    for (int i = 0; i < 4; i++)
        #pragma unroll
        for (int j = 0; j < 4; j++)
            #pragma unroll
            for (int q = 0; q < 4; q++) acc[i][j][q] = 0.f;

    const int ktiles = Kd / 16;

    {
        CP_ASYNC16(dA, Arow + ka);
        CP_ASYNC16(dA + 16, Arow + ka + 4);
        CP_ASYNC16(dB, Bp + (size_t)rb * N + n0 + cb);
        CP_ASYNC16(dB + BPITCH * 8 * 4, Bp + (size_t)(rb + 8) * N + n0 + cb);
        CP_COMMIT();
    }

    for (int t = 0; t < ktiles; t++) {
        const int cur = t & 1;
        if (t + 1 < ktiles) {
            const int nxt = (t + 1) & 1;
            const int k0 = (t + 1) * 16;
            CP_ASYNC16(dA + nxt * stageA, Arow + k0 + ka);
            CP_ASYNC16(dA + nxt * stageA + 16, Arow + k0 + ka + 4);
            CP_ASYNC16(dB + nxt * stageB, Bp + (size_t)(k0 + rb) * N + n0 + cb);
            CP_ASYNC16(dB + nxt * stageB + BPITCH * 8 * 4,
                       Bp + (size_t)(k0 + rb + 8) * N + n0 + cb);
            CP_COMMIT();
            asm volatile("cp.async.wait_group 1;");
        } else {
            asm volatile("cp.async.wait_group 0;");
        }
        __syncthreads();

        const float (*Ab)[APITCH] = As[cur];
        const float (*Bb)[BPITCH] = Bs[cur];

        uint32_t ah[4][4], al[4][4];
        #pragma unroll
        for (int i = 0; i < 4; i++) {
            const float* p = &Ab[wm * 64 + i * 16 + tr][2 * tc];
            float2 x = *(const float2*)p;
            float2 y = *(const float2*)(p + 8 * APITCH);
            float2 z = *(const float2*)(p + 8);
            float2 w = *(const float2*)(p + 8 * APITCH + 8);
            split2(x.x, x.y, ah[i][0], al[i][0]);
            split2(y.x, y.y, ah[i][1], al[i][1]);
            split2(z.x, z.y, ah[i][2], al[i][2]);
            split2(w.x, w.y, ah[i][3], al[i][3]);
        }

        #pragma unroll
        for (int j = 0; j < 4; j++) {
            const int n = wn * 32 + j * 8 + tr;
            uint32_t b0h, b0l, b1h, b1l;
            split2(Bb[2 * tc][n],     Bb[2 * tc + 1][n],     b0h, b0l);
            split2(Bb[8 + 2 * tc][n], Bb[8 + 2 * tc + 1][n], b1h, b1l);
            #pragma unroll
            for (int i = 0; i < 4; i++) {
                mma_bf16(acc[i][j], ah[i][0], ah[i][1], ah[i][2], ah[i][3], b0h, b1h);
                mma_bf16(acc[i][j], ah[i][0], ah[i][1], ah[i][2], ah[i][3], b0l, b1l);
                mma_bf16(acc[i][j], al[i][0], al[i][1], al[i][2], al[i][3], b0h, b1h);
            }
        }
        __syncthreads();
    }

    #pragma unroll
    for (int i = 0; i < 4; i++) {
        const int r = m0 + wm * 64 + i * 16 + tr;
        #pragma unroll
        for (int j = 0; j < 4; j++) {
            const int c = n0 + wn * 32 + j * 8 + tc * 2;
            const float b0 = bp[c], b1 = bp[c + 1];
            if (MODE == 0) {
                float2 v0 = make_float2(acc[i][j][0] + b0, acc[i][j][1] + b1);
                float2 v1 = make_float2(acc[i][j][2] + b0, acc[i][j][3] + b1);
                *(float2*)&C[(size_t)r * N + c] = v0;
                *(float2*)&C[(size_t)(r + 8) * N + c] = v1;
            } else if (MODE == 1) {
                if (r < Me) {
                    float v0 = acc[i][j][0] + b0, v1 = acc[i][j][1] + b1;
                    float2 o;
                    o.x = 0.5f * v0 * (1.0f + erff(v0 * 0.7071067811865475f));
                    o.y = 0.5f * v1 * (1.0f + erff(v1 * 0.7071067811865475f));
                    *(float2*)&C[(size_t)(hbase + r) * N + c] = o;
                }
                if (r + 8 < Me) {
                    float v0 = acc[i][j][2] + b0, v1 = acc[i][j][3] + b1;
                    float2 o;
                    o.x = 0.5f * v0 * (1.0f + erff(v0 * 0.7071067811865475f));
                    o.y = 0.5f * v1 * (1.0f + erff(v1 * 0.7071067811865475f));
                    *(float2*)&C[(size_t)(hbase + r + 8) * N + c] = o;
                }
            } else {
                if (r < Me) {
                    int   tk = tokl[e * Tt + r];
                    float w  = wtl [e * Tt + r];
                    float* Crow = &C[(size_t)tk * N + c];
                    atomicAdd(&Crow[0], w * (acc[i][j][0] + b0));
                    atomicAdd(&Crow[1], w * (acc[i][j][1] + b1));
                }
                if (r + 8 < Me) {
                    int   tk = tokl[e * Tt + r + 8];
                    float w  = wtl [e * Tt + r + 8];
                    float* Crow = &C[(size_t)tk * N + c];
                    atomicAdd(&Crow[0], w * (acc[i][j][2] + b0));
                    atomicAdd(&Crow[1], w * (acc[i][j][3] + b1));
                }
            }
        }
    }
}

// ------------------------- tensor-core flash attention ---------------------
// Block: 64 q-rows of one (b,h); 4 warps x 16 rows. K/V chunks of 64 keys.
// K/V pre-split into bf16x2 hi/lo in smem (packed along mma-k dim).
// Scores and P·V both use the bf16x3 compensated scheme.
#define KPITCH 36   /* = 4 (mod 32): frag bank = 4*tr+tc, conflict-free */
#define VPITCH 72   /* = 8 (mod 32): frag bank = 8*tc+tr, conflict-free */

__global__ __launch_bounds__(128)
void attn_tc(const float* __restrict__ q, const float* __restrict__ k,
             const float* __restrict__ v, float* __restrict__ out)
{
    const int bh = blockIdx.y;
    const int b = bh >> 4, h = bh & 15;
    const int warp = threadIdx.x >> 5, lane = threadIdx.x & 31;
    const int tr = lane >> 2, tc = lane & 3;
    const int qrow = blockIdx.x * 64 + warp * 16;

    __shared__ uint32_t Kh[64][KPITCH], Kl[64][KPITCH];
    __shared__ uint32_t Vh[32][VPITCH], Vl[32][VPITCH];

    // ---- persistent Q fragments (scaled by 1/sqrt(HD), hi/lo split) ----
    uint32_t qh[4][4], ql[4][4];
    {
        const float* q0 = q + ((size_t)(b * Sq + qrow + tr) * Dm + h * HDIM);
        const float* q1 = q0 + 8 * Dm;
        #pragma unroll
        for (int ks = 0; ks < 4; ks++) {
            int d = ks * 16 + 2 * tc;
            float2 x = *(const float2*)(q0 + d);
            float2 y = *(const float2*)(q1 + d);
            float2 z = *(const float2*)(q0 + d + 8);
            float2 w = *(const float2*)(q1 + d + 8);
            split2(x.x * 0.125f, x.y * 0.125f, qh[ks][0], ql[ks][0]);
            split2(y.x * 0.125f, y.y * 0.125f, qh[ks][1], ql[ks][1]);
            split2(z.x * 0.125f, z.y * 0.125f, qh[ks][2], ql[ks][2]);
            split2(w.x * 0.125f, w.y * 0.125f, qh[ks][3], ql[ks][3]);
        }
    }

    float o[8][4];
    #pragma unroll
    for (int j = 0; j < 8; j++)
        #pragma unroll
        for (int qq = 0; qq < 4; qq++) o[j][qq] = 0.f;
    float m0 = -1e30f, m1 = -1e30f, l0 = 0.f, l1 = 0.f;

    for (int t0 = 0; t0 < Sq; t0 += 64) {
        __syncthreads();
        // ---- load K chunk: 64 keys x 64 d, split hi/lo, pack along d ----
        for (int i = threadIdx.x; i < 64 * 16; i += 128) {
            int row = i >> 4, c4 = (i & 15) * 4;
            float4 kv = *(const float4*)(k + (size_t)(b * Sq + t0 + row) * Dm
                                           + h * HDIM + c4);
            uint32_t h0, l0_, h1, l1_;
            split2(kv.x, kv.y, h0, l0_);
            split2(kv.z, kv.w, h1, l1_);
            *(uint2*)&Kh[row][c4 >> 1] = make_uint2(h0, h1);
            *(uint2*)&Kl[row][c4 >> 1] = make_uint2(l0_, l1_);
        }
        // ---- load V chunk: pack pairs along key dim ----
        for (int i = threadIdx.x; i < 32 * 16; i += 128) {
            int kk = i >> 4, c4 = (i & 15) * 4;
            const float* vp = v + (size_t)(b * Sq + t0 + 2 * kk) * Dm
                                + h * HDIM + c4;
            float4 r0 = *(const float4*)vp;
            float4 r1 = *(const float4*)(vp + Dm);
            uint32_t hh0, ll0, hh1, ll1, hh2, ll2, hh3, ll3;
            split2(r0.x, r1.x, hh0, ll0);
            split2(r0.y, r1.y, hh1, ll1);
            split2(r0.z, r1.z, hh2, ll2);
            split2(r0.w, r1.w, hh3, ll3);
            *(uint4*)&Vh[kk][c4] = make_uint4(hh0, hh1, hh2, hh3);
            *(uint4*)&Vl[kk][c4] = make_uint4(ll0, ll1, ll2, ll3);
        }
        __syncthreads();

        // ---- scores: S = Q K^T (bf16x3) ----
        float sc[8][4];
        #pragma unroll
        for (int j = 0; j < 8; j++) {
            float c[4] = {0.f, 0.f, 0.f, 0.f};
            const int n = j * 8 + tr;
            #pragma unroll
            for (int ks = 0; ks < 4; ks++) {
                uint32_t b0h = Kh[n][8 * ks + tc],     b1h = Kh[n][8 * ks + 4 + tc];
                uint32_t b0l = Kl[n][8 * ks + tc],     b1l = Kl[n][8 * ks + 4 + tc];
                mma_bf16(c, qh[ks][0], qh[ks][1], qh[ks][2], qh[ks][3], b0h, b1h);
                mma_bf16(c, qh[ks][0], qh[ks][1], qh[ks][2], qh[ks][3], b0l, b1l);
                mma_bf16(c, ql[ks][0], ql[ks][1], ql[ks][2], ql[ks][3], b0h, b1h);
            }
            sc[j][0] = c[0]; sc[j][1] = c[1]; sc[j][2] = c[2]; sc[j][3] = c[3];
        }

        // ---- online softmax ----
        float mt0 = -1e30f, mt1 = -1e30f;
        #pragma unroll
        for (int j = 0; j < 8; j++) {
            mt0 = fmaxf(mt0, fmaxf(sc[j][0], sc[j][1]));
            mt1 = fmaxf(mt1, fmaxf(sc[j][2], sc[j][3]));
        }
        mt0 = fmaxf(mt0, __shfl_xor_sync(0xffffffffu, mt0, 1));
        mt0 = fmaxf(mt0, __shfl_xor_sync(0xffffffffu, mt0, 2));
        mt1 = fmaxf(mt1, __shfl_xor_sync(0xffffffffu, mt1, 1));
        mt1 = fmaxf(mt1, __shfl_xor_sync(0xffffffffu, mt1, 2));

        float mn0 = fmaxf(m0, mt0), mn1 = fmaxf(m1, mt1);
        float a0 = __expf(m0 - mn0), a1 = __expf(m1 - mn1);
        l0 *= a0; l1 *= a1;
        #pragma unroll
        for (int j = 0; j < 8; j++) {
            o[j][0] *= a0; o[j][1] *= a0;
            o[j][2] *= a1; o[j][3] *= a1;
        }
        m0 = mn0; m1 = mn1;

        #pragma unroll
        for (int j = 0; j < 8; j++) {
            sc[j][0] = __expf(sc[j][0] - m0);
            sc[j][1] = __expf(sc[j][1] - m0);
            sc[j][2] = __expf(sc[j][2] - m1);
            sc[j][3] = __expf(sc[j][3] - m1);
            l0 += sc[j][0] + sc[j][1];
            l1 += sc[j][2] + sc[j][3];
        }

        // ---- P fragments straight from accumulator layout ----
        uint32_t ph[4][4], pl[4][4];
        #pragma unroll
        for (int ks = 0; ks < 4; ks++) {
            split2(sc[2 * ks][0],     sc[2 * ks][1],     ph[ks][0], pl[ks][0]);
            split2(sc[2 * ks][2],     sc[2 * ks][3],     ph[ks][1], pl[ks][1]);
            split2(sc[2 * ks + 1][0], sc[2 * ks + 1][1], ph[ks][2], pl[ks][2]);
            split2(sc[2 * ks + 1][2], sc[2 * ks + 1][3], ph[ks][3], pl[ks][3]);
        }

        // ---- O += P V (bf16x3) ----
        #pragma unroll
        for (int jd = 0; jd < 8; jd++) {
            const int d = jd * 8 + tr;
            #pragma unroll
            for (int ks = 0; ks < 4; ks++) {
                uint32_t b0h = Vh[8 * ks + tc][d], b1h = Vh[8 * ks + 4 + tc][d];
                uint32_t b0l = Vl[8 * ks + tc][d], b1l = Vl[8 * ks + 4 + tc][d];
                mma_bf16(o[jd], ph[ks][0], ph[ks][1], ph[ks][2], ph[ks][3], b0h, b1h);
                mma_bf16(o[jd], ph[ks][0], ph[ks][1], ph[ks][2], ph[ks][3], b0l, b1l);
                mma_bf16(o[jd], pl[ks][0], pl[ks][1], pl[ks][2], pl[ks][3], b0h, b1h);
            }
        }
    }

    // ---- finalize ----
    l0 += __shfl_xor_sync(0xffffffffu, l0, 1);
    l0 += __shfl_xor_sync(0xffffffffu, l0, 2);
    l1 += __shfl_xor_sync(0xffffffffu, l1, 1);
    l1 += __shfl_xor_sync(0xffffffffu, l1, 2);
    float inv0 = 1.f / l0, inv1 = 1.f / l1;

    float* o0 = out + ((size_t)(b * Sq + qrow + tr) * Dm + h * HDIM);
    float* o1 = o0 + 8 * Dm;
    #pragma unroll
    for (int jd = 0; jd < 8; jd++) {
        int d = jd * 8 + 2 * tc;
        *(float2*)(o0 + d) = make_float2(o[jd][0] * inv0, o[jd][1] * inv0);
        *(float2*)(o1 + d) = make_float2(o[jd][2] * inv1, o[jd][3] * inv1);
    }
}

// ------------------------- LayerNorm(a + b) --------------------------------
__global__ __launch_bounds__(256)
void ln_kernel(const float* __restrict__ a, const float* __restrict__ bsrc,
               const float* __restrict__ g, const float* __restrict__ beta,
               float* __restrict__ out)
{
    const int row = blockIdx.x;
    __shared__ float buf[Dm];
    __shared__ float red[8];
    const int tid = threadIdx.x;
    const int lane = tid & 31, wid = tid >> 5;

    float s = 0.f;
    for (int d = tid; d < Dm; d += 256) {
        float v = a[(size_t)row * Dm + d] + bsrc[(size_t)row * Dm + d];
        buf[d] = v;
        s += v;
    }
    #pragma unroll
    for (int o = 16; o; o >>= 1) s += __shfl_xor_sync(0xffffffffu, s, o);
    if (lane == 0) red[wid] = s;
    __syncthreads();
    float mean = (red[0]+red[1]+red[2]+red[3]+red[4]+red[5]+red[6]+red[7]) * (1.f/Dm);

    float s2 = 0.f;
    for (int d = tid; d < Dm; d += 256) {
        float c = buf[d] - mean;
        s2 += c * c;
    }
    #pragma unroll
    for (int o = 16; o; o >>= 1) s2 += __shfl_xor_sync(0xffffffffu, s2, o);
    __syncthreads();
    if (lane == 0) red[wid] = s2;
    __syncthreads();
    float var = (red[0]+red[1]+red[2]+red[3]+red[4]+red[5]+red[6]+red[7]) * (1.f/Dm);
    float rstd = rsqrtf(var + 1e-5f);

    for (int d = tid; d < Dm; d += 256)
        out[(size_t)row * Dm + d] = (buf[d] - mean) * rstd * g[d] + beta[d];
}

// ------------------------- gating + top-2 routing --------------------------
__global__ __launch_bounds__(128)
void gate_kernel(const float* __restrict__ x1, const float* __restrict__ gW,
                 const float* __restrict__ gb, int* __restrict__ cnt,
                 int* __restrict__ tokl, float* __restrict__ wtl,
                 float* __restrict__ gsum)
{
    const int t = blockIdx.x;
    __shared__ float xs[Dm];
    __shared__ float lg[Ee];
    const int tid = threadIdx.x;
    for (int d = tid; d < Dm; d += 128) xs[d] = x1[(size_t)t * Dm + d];
    __syncthreads();

    const int lane = tid & 31, wid = tid >> 5;
    for (int e = wid; e < Ee; e += 4) {
        float s = 0.f;
        for (int d = lane; d < Dm; d += 32) s += xs[d] * gW[d * Ee + e];
        #pragma unroll
        for (int o = 16; o; o >>= 1) s += __shfl_xor_sync(0xffffffffu, s, o);
        if (lane == 0) lg[e] = s + gb[e];
    }
    __syncthreads();

    if (tid == 0) {
        float mx = lg[0];
        #pragma unroll
        for (int e = 1; e < Ee; e++) mx = fmaxf(mx, lg[e]);
        float sc[Ee];
        float se = 0.f;
        #pragma unroll
        for (int e = 0; e < Ee; e++) { sc[e] = expf(lg[e] - mx); se += sc[e]; }
        float inv = 1.f / se;
        #pragma unroll
        for (int e = 0; e < Ee; e++) sc[e] *= inv;

        int i1 = 0;
        #pragma unroll
        for (int e = 1; e < Ee; e++) if (sc[e] > sc[i1]) i1 = e;
        int i2 = (i1 == 0) ? 1 : 0;
        #pragma unroll
        for (int e = 0; e < Ee; e++) { if (e == i1 || e == i2) continue; if (sc[e] > sc[i2]) i2 = e; }

        float ws = sc[i1] + sc[i2];
        float w1 = sc[i1] / ws, w2 = sc[i2] / ws;
        int p1 = atomicAdd(&cnt[i1], 1); tokl[i1 * Tt + p1] = t; wtl[i1 * Tt + p1] = w1;
        int p2 = atomicAdd(&cnt[i2], 1); tokl[i2 * Tt + p2] = t; wtl[i2 * Tt + p2] = w2;
        #pragma unroll
        for (int e = 0; e < Ee; e++) atomicAdd(&gsum[e], sc[e]);
    }
}

// ------------------------- small helpers -----------------------------------
__global__ void zero_kernel(float* moe, int* cnt, float* gsum)
{
    int i = blockIdx.x * blockDim.x + threadIdx.x;
    int stride = gridDim.x * blockDim.x;
    for (int j = i; j < Tt * Dm; j += stride) moe[j] = 0.f;
    if (i < Ee) { cnt[i] = 0; gsum[i] = 0.f; }
}

__global__ void offsets_kernel(const int* cnt, int* off)
{
    if (threadIdx.x == 0) {
        int s = 0;
        for (int e = 0; e < Ee; e++) { off[e] = s; s += cnt[e]; }
    }
}

__global__ void aux_kernel(const int* cnt, const float* gsum, float* dst)
{
    if (threadIdx.x == 0) {
        float a = 0.f;
        for (int e = 0; e < Ee; e++)
            a += ((float)cnt[e] / (float)(Tt * Kk)) * (gsum[e] / (float)Tt);
        dst[0] = (float)Ee * a;
    }
}

// ------------------------- launch ------------------------------------------
extern "C" void kernel_launch(void* const* d_in, const int* in_sizes, int n_in,
                              void* d_out, int out_size)
{
    const float* x     = (const float*)d_in[0];
    const float* Wq    = (const float*)d_in[1];
    const float* bq    = (const float*)d_in[2];
    const float* Wk    = (const float*)d_in[3];
    const float* bk    = (const float*)d_in[4];
    const float* Wv    = (const float*)d_in[5];
    const float* bv    = (const float*)d_in[6];
    const float* Wo    = (const float*)d_in[7];
    const float* bo    = (const float*)d_in[8];
    const float* g1    = (const float*)d_in[9];
    const float* beta1 = (const float*)d_in[10];
    const float* gateW = (const float*)d_in[11];
    const float* gateb = (const float*)d_in[12];
    const float* eW1   = (const float*)d_in[13];
    const float* eb1   = (const float*)d_in[14];
    const float* eW2   = (const float*)d_in[15];
    const float* eb2   = (const float*)d_in[16];
    const float* g2    = (const float*)d_in[17];
    const float* beta2 = (const float*)d_in[18];
    float* out = (float*)d_out;

    float *pq, *pk, *pv, *pat, *ppr, *px1, *pmoe, *ph, *pwt, *pgs;
    int *ptok, *pcnt, *poff;
    cudaGetSymbolAddress((void**)&pq,   g_q);
    cudaGetSymbolAddress((void**)&pk,   g_k);
    cudaGetSymbolAddress((void**)&pv,   g_v);
    cudaGetSymbolAddress((void**)&pat,  g_att);
    cudaGetSymbolAddress((void**)&ppr,  g_prj);
    cudaGetSymbolAddress((void**)&px1,  g_x1);
    cudaGetSymbolAddress((void**)&pmoe, g_moe);
    cudaGetSymbolAddress((void**)&ph,   g_h);
    cudaGetSymbolAddress((void**)&ptok, g_tok);
    cudaGetSymbolAddress((void**)&pwt,  g_wt);
    cudaGetSymbolAddress((void**)&pcnt, g_cnt);
    cudaGetSymbolAddress((void**)&poff, g_off);
    cudaGetSymbolAddress((void**)&pgs,  g_gsum);

    dim3 gQ(Dm / 128, Tt / 128, 1);   // (8, 64)

    // QKV projections (bf16x3 tensor cores)
    gemm_tc<0><<<gQ, 256>>>(x, Wq, bq, pq, Tt, Dm, Dm, nullptr, nullptr, nullptr, nullptr);
    gemm_tc<0><<<gQ, 256>>>(x, Wk, bk, pk, Tt, Dm, Dm, nullptr, nullptr, nullptr, nullptr);
    gemm_tc<0><<<gQ, 256>>>(x, Wv, bv, pv, Tt, Dm, Dm, nullptr, nullptr, nullptr, nullptr);

    // tensor-core flash attention
    attn_tc<<<dim3(Sq / 64, Bc * Hh), 128>>>(pq, pk, pv, pat);

    // output projection + residual LN1
    gemm_tc<0><<<gQ, 256>>>(pat, Wo, bo, ppr, Tt, Dm, Dm, nullptr, nullptr, nullptr, nullptr);
    ln_kernel<<<Tt, 256>>>(x, ppr, g1, beta1, px1);

    // MoE: routing + sparse expert GEMMs
    zero_kernel<<<2048, 256>>>(pmoe, pcnt, pgs);
    gate_kernel<<<Tt, 128>>>(px1, gateW, gateb, pcnt, ptok, pwt, pgs);
    offsets_kernel<<<1, 32>>>(pcnt, poff);
    gemm_tc<1><<<dim3(Ff / 128, Tt / 128, Ee), 256>>>(
        px1, eW1, eb1, ph, Tt, Ff, Dm, pcnt, poff, ptok, pwt);
    gemm_tc<2><<<dim3(Dm / 128, Tt / 128, Ee), 256>>>(
        ph, eW2, eb2, pmoe, Tt, Dm, Ff, pcnt, poff, ptok, pwt);

    // final residual LN2 -> output
    ln_kernel<<<Tt, 256>>>(px1, pmoe, g2, beta2, out);

    // aux loss scalar appended after the [B,S,D] tensor
    if (out_size > Tt * Dm)
        aux_kernel<<<1, 32>>>(pcnt, pgs, out + (size_t)Tt * Dm);
}